// round 15
// baseline (speedup 1.0000x reference)
#include <cuda_runtime.h>
#include <cuda_fp16.h>
#include <math.h>
#include <stdint.h>

// ---------------- problem constants ----------------
#define NL     6
#define DMODEL 1024
#define DFF    4096
#define VOC    32000
#define NH     16
#define HDIM   64
#define BATCH  2
#define TSEQ   1024
#define MTOK   (BATCH*TSEQ)   // 2048
#define NSLOTS 296            // 148 SMs x 2 CTAs

// ---------------- scratch (static device globals; no allocation) ----------------
__device__ float g_x[MTOK * DMODEL];

__device__ __align__(16) half g_h  [MTOK * DMODEL];
__device__ __align__(16) half g_qkv[(size_t)MTOK * 3 * DMODEL];
__device__ __align__(16) half g_o  [MTOK * DMODEL];
__device__ __align__(16) half g_f  [(size_t)MTOK * DFF];

__device__ __align__(16) half g_wq[(size_t)NL*3*DMODEL*DMODEL];
__device__ __align__(16) half g_wo[(size_t)NL*DMODEL*DMODEL];
__device__ __align__(16) half g_w1[(size_t)NL*DFF*DMODEL];
__device__ __align__(16) half g_w2[(size_t)NL*DMODEL*DFF];
__device__ __align__(16) half g_eh[(size_t)VOC*DMODEL];

// ---------------- helpers ----------------
__device__ __forceinline__ uint32_t packh(half a, half b) {
    __half2 t; t.x = a; t.y = b;
    return *(uint32_t*)&t;
}

__device__ __forceinline__ void cp_async16(uint32_t s, const void* g) {
    asm volatile("cp.async.cg.shared.global [%0], [%1], 16;\n" :: "r"(s), "l"(g));
}
__device__ __forceinline__ void cp_commit() { asm volatile("cp.async.commit_group;\n"); }
template<int N> __device__ __forceinline__ void cp_wait() {
    asm volatile("cp.async.wait_group %0;\n" :: "n"(N));
}

__device__ __forceinline__ void ldsm4(uint32_t* r, uint32_t addr) {
    asm volatile("ldmatrix.sync.aligned.m8n8.x4.shared.b16 {%0,%1,%2,%3}, [%4];\n"
        : "=r"(r[0]), "=r"(r[1]), "=r"(r[2]), "=r"(r[3]) : "r"(addr));
}
__device__ __forceinline__ void ldsm4t(uint32_t* r, uint32_t addr) {
    asm volatile("ldmatrix.sync.aligned.m8n8.x4.trans.shared.b16 {%0,%1,%2,%3}, [%4];\n"
        : "=r"(r[0]), "=r"(r[1]), "=r"(r[2]), "=r"(r[3]) : "r"(addr));
}

__device__ __forceinline__ void mma16816(float* c, const uint32_t* a, uint32_t b0, uint32_t b1) {
    asm volatile(
        "mma.sync.aligned.m16n8k16.row.col.f32.f16.f16.f32 "
        "{%0,%1,%2,%3}, {%4,%5,%6,%7}, {%8,%9}, {%0,%1,%2,%3};\n"
        : "+f"(c[0]), "+f"(c[1]), "+f"(c[2]), "+f"(c[3])
        : "r"(a[0]), "r"(a[1]), "r"(a[2]), "r"(a[3]), "r"(b0), "r"(b1));
}

// ---------------- fused fp32 -> fp16 conversion (8 elems/thread, MLP=2) ----------------
__global__ __launch_bounds__(256) void cvt_all(
    const float* __restrict__ x0, half* __restrict__ h0, size_t n0,
    const float* __restrict__ x1, half* __restrict__ h1, size_t n1,
    const float* __restrict__ x2, half* __restrict__ h2, size_t n2,
    const float* __restrict__ x3, half* __restrict__ h3, size_t n3,
    const float* __restrict__ x4, half* __restrict__ h4, size_t n4)
{
    size_t i = ((size_t)blockIdx.x * 256 + threadIdx.x) * 8;
    const float* s; half* d;
    if (i < n0)              { s = x0; d = h0; }
    else if ((i -= n0) < n1) { s = x1; d = h1; }
    else if ((i -= n1) < n2) { s = x2; d = h2; }
    else if ((i -= n2) < n3) { s = x3; d = h3; }
    else { i -= n3; if (i >= n4) return; s = x4; d = h4; }
    float4 va = *(const float4*)(s + i);
    float4 vb = *(const float4*)(s + i + 4);
    uint4 o;
    o.x = packh(__float2half(va.x), __float2half(va.y));
    o.y = packh(__float2half(va.z), __float2half(va.w));
    o.z = packh(__float2half(vb.x), __float2half(vb.y));
    o.w = packh(__float2half(vb.z), __float2half(vb.w));
    *(uint4*)(d + i) = o;
}

// ---------------- fp16 GEMM (mma.sync), BK=64, 3-stage, persistent tiles ----------------
// C[M,N] = A[M,K] * B[N,K]^T
// BM x 128 tile, BK=64, 256 threads (8 warps, 2x4), warp tile (BM/2) x 32.
// Grid-stride over tiles: launch min(tiles, NSLOTS) CTAs.
#define EPI_STORE  0
#define EPI_ADD    1
#define EPI_GELU   2
#define EPI_STOREH 3

template<int BM, int EPI>
__global__ __launch_bounds__(256) void gemm_f16(
    const half* __restrict__ A, const half* __restrict__ B,
    float* __restrict__ C, half* __restrict__ Ch,
    int M, int N, int K)
{
    constexpr int NS = 3;                        // pipeline stages
    constexpr int MT = BM / 32;                  // m-tiles (16-row) per warp
    constexpr uint32_t ABYTES = (uint32_t)BM * 128;
    constexpr uint32_t STAGE  = ABYTES + 16384u; // [A | B 16KB] (rows x 128B)

    extern __shared__ uint8_t smem[];
    const uint32_t smem_u32 = (uint32_t)__cvta_generic_to_shared(smem);

    const int tid  = threadIdx.x;
    const int lane = tid & 31;
    const int wid  = tid >> 5;
    const int wm   = wid & 1;
    const int wn   = wid >> 1;

    const int ntx = N >> 7;
    const int nty = M / BM;
    const int ntiles_total = ntx * nty;
    const int ntiles = K >> 6;

    for (int tile = blockIdx.x; tile < ntiles_total; tile += gridDim.x) {
        const int bm = (tile / ntx) * BM;
        const int bn = (tile % ntx) * 128;

        const half* Ab = A + (size_t)bm * K;
        const half* Bb = B + (size_t)bn * K;

        float acc[MT][4][4];
#pragma unroll
        for (int a = 0; a < MT; a++)
#pragma unroll
            for (int b = 0; b < 4; b++)
#pragma unroll
                for (int c = 0; c < 4; c++) acc[a][b][c] = 0.f;

        auto load_stage = [&](int st, int k0) {
            uint32_t base = smem_u32 + (uint32_t)st * STAGE;
#pragma unroll
            for (int i = 0; i < BM/32; i++) {            // A: BM*8 chunks
                int idx = tid * (BM/32) + i;
                int r = idx >> 3, c = idx & 7;
                size_t go = (size_t)r * K + k0 + c * 8;
                uint32_t so = base + r * 128 + (((uint32_t)(c ^ (r & 7))) << 4);
                cp_async16(so, Ab + go);
            }
#pragma unroll
            for (int i = 0; i < 4; i++) {                // B: 1024 chunks
                int idx = tid * 4 + i;
                int r = idx >> 3, c = idx & 7;
                size_t go = (size_t)r * K + k0 + c * 8;
                uint32_t so = base + ABYTES + r * 128 + (((uint32_t)(c ^ (r & 7))) << 4);
                cp_async16(so, Bb + go);
            }
        };

        // prologue: fill NS-1 stages, one commit group each
#pragma unroll
        for (int t = 0; t < NS - 1; t++) {
            load_stage(t, t << 6);
            cp_commit();
        }

        int st = 0, stn = NS - 1;
        for (int t = 0; t < ntiles; t++) {
            cp_wait<NS - 2>();
            __syncthreads();

            int tn = t + NS - 1;
            if (tn < ntiles) load_stage(stn, tn << 6);
            cp_commit();

            const uint32_t bA = smem_u32 + (uint32_t)st * STAGE;
            const uint32_t bB = bA + ABYTES;

#pragma unroll
            for (int s = 0; s < 4; s++) {
                uint32_t af[MT][4];
#pragma unroll
                for (int mt = 0; mt < MT; mt++) {
                    int row = wm * (BM/2) + mt * 16 + (lane & 15);
                    int ch  = 2 * s + (lane >> 4);
                    uint32_t off = row * 128 + (((uint32_t)(ch ^ (row & 7))) << 4);
                    ldsm4(af[mt], bA + off);
                }
                uint32_t bf[2][4];
#pragma unroll
                for (int p = 0; p < 2; p++) {
                    int row = wn * 32 + p * 16 + (lane & 15);
                    int ch  = 2 * s + (lane >> 4);
                    uint32_t off = row * 128 + (((uint32_t)(ch ^ (row & 7))) << 4);
                    ldsm4(bf[p], bB + off);
                }
#pragma unroll
                for (int mt = 0; mt < MT; mt++)
#pragma unroll
                    for (int nt = 0; nt < 4; nt++) {
                        int p = nt >> 1, q = nt & 1;
                        mma16816(acc[mt][nt], af[mt], bf[p][q], bf[p][q + 2]);
                    }
            }

            if (++st == NS) st = 0;
            if (++stn == NS) stn = 0;
        }

        __syncthreads();   // all warps done reading smem before next tile overwrites

        // --- epilogue (registers -> gmem only) ---
#pragma unroll
        for (int mt = 0; mt < MT; mt++) {
#pragma unroll
            for (int nt = 0; nt < 4; nt++) {
                int row = bm + wm * (BM/2) + mt * 16 + (lane >> 2);
                int col = bn + wn * 32 + nt * 8 + (lane & 3) * 2;
                size_t i0 = (size_t)row * N + col;
                size_t i1 = i0 + (size_t)8 * N;
                float* c = acc[mt][nt];
                if (EPI == EPI_STORE) {
                    *(float2*)(C + i0) = make_float2(c[0], c[1]);
                    *(float2*)(C + i1) = make_float2(c[2], c[3]);
                } else if (EPI == EPI_ADD) {
                    float2 o0 = *(const float2*)(C + i0);
                    float2 o1 = *(const float2*)(C + i1);
                    o0.x += c[0]; o0.y += c[1];
                    o1.x += c[2]; o1.y += c[3];
                    *(float2*)(C + i0) = o0;
                    *(float2*)(C + i1) = o1;
                } else if (EPI == EPI_GELU) {
#pragma unroll
                    for (int e = 0; e < 4; e += 2) {
                        size_t ii = (e == 0) ? i0 : i1;
                        float v0 = c[e], v1 = c[e+1];
                        float q0 = 0.5f * v0 * (1.f + erff(v0 * 0.70710678118654752f));
                        float q1 = 0.5f * v1 * (1.f + erff(v1 * 0.70710678118654752f));
                        *(uint32_t*)(Ch + ii) = packh(__float2half(q0), __float2half(q1));
                    }
                } else {  // EPI_STOREH
                    *(uint32_t*)(Ch + i0) = packh(__float2half(c[0]), __float2half(c[1]));
                    *(uint32_t*)(Ch + i1) = packh(__float2half(c[2]), __float2half(c[3]));
                }
            }
        }
    }
}

// ---------------- flash attention (single fp16, mma.sync, 3-stage KV) ----------------
__global__ __launch_bounds__(256) void flash_kernel(
    const half* __restrict__ qkv, half* __restrict__ o)
{
    extern __shared__ uint8_t fsm[];
    const uint32_t sb  = (uint32_t)__cvta_generic_to_shared(fsm);
    const uint32_t sQ  = sb;                  // 128 x 64 halves = 16KB
    const uint32_t sKV = sb + 16384;          // + stage*16384 : [K 8KB | V 8KB], 3 stages

    const int tid = threadIdx.x, lane = tid & 31, w = tid >> 5;
    const int qi = (int)gridDim.x - 1 - (int)blockIdx.x;   // big tiles first
    const int bh = blockIdx.y;
    const int b = bh >> 4, h = bh & 15;
    const int qbase = qi * 128;
    const int nkb = (qbase + 128) >> 6;       // always >= 2

    const size_t tb = (size_t)b * TSEQ;
    const half* Q_ = qkv + tb * 3 * DMODEL + h * HDIM;
    const half* K_ = Q_ + DMODEL;
    const half* V_ = Q_ + 2 * DMODEL;

    auto load_kv = [&](int buf, int kb) {
        uint32_t base = sKV + (uint32_t)buf * 16384;
#pragma unroll
        for (int i = 0; i < 2; i++) {
            int idx = tid * 2 + i;          // 0..511
            int r = idx >> 3, c = idx & 7;
            size_t go = (size_t)(kb * 64 + r) * 3 * DMODEL + c * 8;
            uint32_t so = r * 128 + (((uint32_t)(c ^ (r & 7))) << 4);
            cp_async16(base + so,        K_ + go);
            cp_async16(base + 8192 + so, V_ + go);
        }
    };

    // prologue: Q + KV0 in group 0, KV1 in group 1
#pragma unroll
    for (int i = 0; i < 4; i++) {
        int idx = tid * 4 + i;              // 0..1023
        int r = idx >> 3, c = idx & 7;
        size_t go = (size_t)(qbase + r) * 3 * DMODEL + c * 8;
        uint32_t so = r * 128 + (((uint32_t)(c ^ (r & 7))) << 4);
        cp_async16(sQ + so, Q_ + go);
    }
    load_kv(0, 0);
    cp_commit();                 // group 0
    load_kv(1, 1);
    cp_commit();                 // group 1

    cp_wait<1>();                // group 0 (Q + KV0) complete
    __syncthreads();

    uint32_t qf[4][4];
#pragma unroll
    for (int s = 0; s < 4; s++) {
        int r = 16 * w + (lane & 15);
        int c = 2 * s + (lane >> 4);
        uint32_t so = r * 128 + (((uint32_t)(c ^ (r & 7))) << 4);
        ldsm4(qf[s], sQ + so);
    }

    float oacc[8][4];
#pragma unroll
    for (int j = 0; j < 8; j++)
#pragma unroll
        for (int c = 0; c < 4; c++) oacc[j][c] = 0.f;
    float mrow0 = -1e30f, mrow1 = -1e30f, lrow0 = 0.f, lrow1 = 0.f;
    const int r0 = qbase + 16 * w + (lane >> 2);

    int st = 0, stn = 2;
    for (int kb = 0; kb < nkb; kb++) {
        cp_wait<1>();                       // group kb complete
        __syncthreads();                    // all warps done reading stage (kb-1)%3

        int tn = kb + 2;
        if (tn < nkb) load_kv(stn, tn);
        cp_commit();                        // always commit (empty in tail)

        if (kb * 64 <= qbase + 16 * w + 15) {
            uint32_t base = sKV + (uint32_t)st * 16384;
            float sacc[8][4];
#pragma unroll
            for (int j = 0; j < 8; j++)
#pragma unroll
                for (int c = 0; c < 4; c++) sacc[j][c] = 0.f;

#pragma unroll
            for (int p = 0; p < 4; p++) {
                int rr = 16 * p + (lane & 15);
#pragma unroll
                for (int s = 0; s < 4; s++) {
                    int cc = 2 * s + (lane >> 4);
                    uint32_t so = rr * 128 + (((uint32_t)(cc ^ (rr & 7))) << 4);
                    uint32_t k4[4];
                    ldsm4(k4, base + so);
                    mma16816(sacc[2*p],   qf[s], k4[0], k4[2]);
                    mma16816(sacc[2*p+1], qf[s], k4[1], k4[3]);
                }
            }
            int cbase = kb * 64 + 2 * (lane & 3);
#pragma unroll
            for (int j = 0; j < 8; j++) {
                int c0 = cbase + 8 * j;
                sacc[j][0] = (c0     <= r0    ) ? sacc[j][0] * 0.125f : -1e30f;
                sacc[j][1] = (c0 + 1 <= r0    ) ? sacc[j][1] * 0.125f : -1e30f;
                sacc[j][2] = (c0     <= r0 + 8) ? sacc[j][2] * 0.125f : -1e30f;
                sacc[j][3] = (c0 + 1 <= r0 + 8) ? sacc[j][3] * 0.125f : -1e30f;
            }
            float mx0 = -1e30f, mx1 = -1e30f;
#pragma unroll
            for (int j = 0; j < 8; j++) {
                mx0 = fmaxf(mx0, fmaxf(sacc[j][0], sacc[j][1]));
                mx1 = fmaxf(mx1, fmaxf(sacc[j][2], sacc[j][3]));
            }
            mx0 = fmaxf(mx0, __shfl_xor_sync(0xffffffffu, mx0, 1));
            mx0 = fmaxf(mx0, __shfl_xor_sync(0xffffffffu, mx0, 2));
            mx1 = fmaxf(mx1, __shfl_xor_sync(0xffffffffu, mx1, 1));
            mx1 = fmaxf(mx1, __shfl_xor_sync(0xffffffffu, mx1, 2));
            float mn0 = fmaxf(mrow0, mx0), mn1 = fmaxf(mrow1, mx1);
            float al0 = __expf(mrow0 - mn0), al1 = __expf(mrow1 - mn1);
            mrow0 = mn0; mrow1 = mn1;

            uint32_t ph[8][2];
            float ls0 = 0.f, ls1 = 0.f;
#pragma unroll
            for (int j = 0; j < 8; j++) {
                float p0 = __expf(sacc[j][0] - mn0);
                float p1 = __expf(sacc[j][1] - mn0);
                float p2 = __expf(sacc[j][2] - mn1);
                float p3 = __expf(sacc[j][3] - mn1);
                ls0 += p0 + p1; ls1 += p2 + p3;
                ph[j][0] = packh(__float2half(p0), __float2half(p1));
                ph[j][1] = packh(__float2half(p2), __float2half(p3));
            }
            ls0 += __shfl_xor_sync(0xffffffffu, ls0, 1);
            ls0 += __shfl_xor_sync(0xffffffffu, ls0, 2);
            ls1 += __shfl_xor_sync(0xffffffffu, ls1, 1);
            ls1 += __shfl_xor_sync(0xffffffffu, ls1, 2);
            lrow0 = lrow0 * al0 + ls0;
            lrow1 = lrow1 * al1 + ls1;
#pragma unroll
            for (int j = 0; j < 8; j++) {
                oacc[j][0] *= al0; oacc[j][1] *= al0;
                oacc[j][2] *= al1; oacc[j][3] *= al1;
            }
            // P @ V
#pragma unroll
            for (int pv = 0; pv < 4; pv++) {
#pragma unroll
                for (int s = 0; s < 4; s++) {
                    int tok = 16 * s + ((lane >> 3) & 1) * 8 + (lane & 7);
                    int dc  = 16 * pv + (lane >> 4) * 8;
                    uint32_t so = tok * 128 + ((((uint32_t)(dc >> 3)) ^ (uint32_t)(tok & 7)) << 4);
                    uint32_t v4[4];
                    ldsm4t(v4, base + 8192 + so);
                    uint32_t pa[4] = {ph[2*s][0], ph[2*s][1], ph[2*s+1][0], ph[2*s+1][1]};
                    mma16816(oacc[2*pv],   pa, v4[0], v4[1]);
                    mma16816(oacc[2*pv+1], pa, v4[2], v4[3]);
                }
            }
        }

        if (++st == 3) st = 0;
        if (++stn == 3) stn = 0;
    }

    float rl0 = 1.f / lrow0, rl1 = 1.f / lrow1;
    size_t ob0 = (tb + r0) * (size_t)DMODEL + h * HDIM + 2 * (lane & 3);
    size_t ob1 = ob0 + 8 * (size_t)DMODEL;
#pragma unroll
    for (int j = 0; j < 8; j++) {
        *(uint32_t*)(o + ob0 + 8 * j) =
            packh(__float2half(oacc[j][0] * rl0), __float2half(oacc[j][1] * rl0));
        *(uint32_t*)(o + ob1 + 8 * j) =
            packh(__float2half(oacc[j][2] * rl1), __float2half(oacc[j][3] * rl1));
    }
}

// ---------------- embedding ----------------
__global__ void embed_kernel(const int* __restrict__ idx,
                             const float* __restrict__ tok,
                             const float* __restrict__ pos,
                             float* __restrict__ x)
{
    int t = blockIdx.x;
    int token = idx[t];
    const float* tr = tok + (size_t)token * DMODEL;
    const float* pr = pos + (size_t)(t & (TSEQ - 1)) * DMODEL;
    float* xr = x + (size_t)t * DMODEL;
    for (int d = threadIdx.x; d < DMODEL; d += blockDim.x)
        xr[d] = tr[d] + pr[d];
}

// ---------------- layernorm: warp per row, 8 rows/CTA ----------------
__global__ __launch_bounds__(256) void layernorm_kernel(
    const float* __restrict__ x, half* __restrict__ y,
    const float* __restrict__ w, const float* __restrict__ bvec)
{
    int lane = threadIdx.x & 31, wid = threadIdx.x >> 5;
    int row = blockIdx.x * 8 + wid;
    const float4* px = (const float4*)(x + (size_t)row * DMODEL);

    float4 v[8];
    float s = 0.f, ss = 0.f;
#pragma unroll
    for (int c = 0; c < 8; c++) {
        v[c] = px[lane + c * 32];
        s  += v[c].x + v[c].y + v[c].z + v[c].w;
        ss += v[c].x*v[c].x + v[c].y*v[c].y + v[c].z*v[c].z + v[c].w*v[c].w;
    }
#pragma unroll
    for (int o = 16; o; o >>= 1) {
        s  += __shfl_xor_sync(0xffffffffu, s,  o);
        ss += __shfl_xor_sync(0xffffffffu, ss, o);
    }
    float mean = s * (1.f / DMODEL);
    float var  = ss * (1.f / DMODEL) - mean * mean;
    float inv  = rsqrtf(var + 1e-5f);

    half* py = y + (size_t)row * DMODEL;
#pragma unroll
    for (int c = 0; c < 8; c++) {
        int j = (lane + c * 32) * 4;
        float4 wv = *(const float4*)(w + j);
        float4 bv = *(const float4*)(bvec + j);
        float y0 = (v[c].x - mean) * inv * wv.x + bv.x;
        float y1 = (v[c].y - mean) * inv * wv.y + bv.y;
        float y2 = (v[c].z - mean) * inv * wv.z + bv.z;
        float y3 = (v[c].w - mean) * inv * wv.w + bv.w;
        uint2 pk;
        pk.x = packh(__float2half(y0), __float2half(y1));
        pk.y = packh(__float2half(y2), __float2half(y3));
        *(uint2*)(py + j) = pk;
    }
}

// ---------------- launch ----------------
static inline int pgrid(int tiles) { return tiles < NSLOTS ? tiles : NSLOTS; }

extern "C" void kernel_launch(void* const* d_in, const int* in_sizes, int n_in,
                              void* d_out, int out_size)
{
    (void)in_sizes; (void)n_in; (void)out_size;
    const int*   idx     = (const int*)  d_in[0];
    const float* tok_emb = (const float*)d_in[1];
    const float* pos_emb = (const float*)d_in[2];
    const float* ln1_w   = (const float*)d_in[3];
    const float* ln1_b   = (const float*)d_in[4];
    const float* qkv_w   = (const float*)d_in[5];
    const float* out_w   = (const float*)d_in[6];
    const float* ln2_w   = (const float*)d_in[7];
    const float* ln2_b   = (const float*)d_in[8];
    const float* ffn1_w  = (const float*)d_in[9];
    const float* ffn2_w  = (const float*)d_in[10];
    const float* lnf_w   = (const float*)d_in[11];
    const float* lnf_b   = (const float*)d_in[12];
    float* out = (float*)d_out;

    float *x;
    half *h, *qv, *o, *f, *wq, *wo, *w1, *w2, *eh;
    cudaGetSymbolAddress((void**)&x,   g_x);
    cudaGetSymbolAddress((void**)&h,   g_h);
    cudaGetSymbolAddress((void**)&qv,  g_qkv);
    cudaGetSymbolAddress((void**)&o,   g_o);
    cudaGetSymbolAddress((void**)&f,   g_f);
    cudaGetSymbolAddress((void**)&wq,  g_wq);
    cudaGetSymbolAddress((void**)&wo,  g_wo);
    cudaGetSymbolAddress((void**)&w1,  g_w1);
    cudaGetSymbolAddress((void**)&w2,  g_w2);
    cudaGetSymbolAddress((void**)&eh,  g_eh);

    cudaFuncSetAttribute(gemm_f16<128,EPI_STOREH>, cudaFuncAttributeMaxDynamicSharedMemorySize, 98304);
    cudaFuncSetAttribute(gemm_f16<64, EPI_ADD>,    cudaFuncAttributeMaxDynamicSharedMemorySize, 73728);
    cudaFuncSetAttribute(gemm_f16<128,EPI_GELU>,   cudaFuncAttributeMaxDynamicSharedMemorySize, 98304);
    cudaFuncSetAttribute(gemm_f16<128,EPI_STORE>,  cudaFuncAttributeMaxDynamicSharedMemorySize, 98304);
    cudaFuncSetAttribute(flash_kernel,             cudaFuncAttributeMaxDynamicSharedMemorySize, 65536);

    // fused weight conversion (single fp16) — one kernel, 8 elems/thread
    {
        const size_t n0 = (size_t)NL*3*DMODEL*DMODEL;
        const size_t n1 = (size_t)NL*DMODEL*DMODEL;
        const size_t n2 = (size_t)NL*DFF*DMODEL;
        const size_t n3 = (size_t)NL*DMODEL*DFF;
        const size_t n4 = (size_t)VOC*DMODEL;
        const size_t total = n0 + n1 + n2 + n3 + n4;
        int blocks = (int)(total / 8 / 256);
        cvt_all<<<blocks, 256>>>(qkv_w, wq, n0, out_w, wo, n1,
                                 ffn1_w, w1, n2, ffn2_w, w2, n3,
                                 tok_emb, eh, n4);
    }

    embed_kernel<<<MTOK, 256>>>(idx, tok_emb, pos_emb, x);

    const int t_qkv = (3*DMODEL/128) * (MTOK/128);   // 24*16  = 384
    const int t_wo  = (DMODEL/128)   * (MTOK/64);    //  8*32  = 256
    const int t_f1  = (DFF/128)      * (MTOK/128);   // 32*16  = 512
    const int t_f2  = (DMODEL/128)   * (MTOK/64);    //  8*32  = 256
    const int t_lm  = (VOC/128)      * (MTOK/128);   // 250*16 = 4000

    for (int l = 0; l < NL; l++) {
        // --- attention block ---
        layernorm_kernel<<<MTOK/8, 256>>>(x, h, ln1_w + l * DMODEL, ln1_b + l * DMODEL);
        gemm_f16<128,EPI_STOREH><<<pgrid(t_qkv), 256, 98304>>>(
            h, wq + (size_t)l*3*DMODEL*DMODEL, nullptr, qv, MTOK, 3*DMODEL, DMODEL);
        flash_kernel<<<dim3(TSEQ/128, BATCH*NH), 256, 65536>>>(qv, o);
        gemm_f16<64,EPI_ADD><<<pgrid(t_wo), 256, 73728>>>(
            o, wo + (size_t)l*DMODEL*DMODEL, x, nullptr, MTOK, DMODEL, DMODEL);
        // --- FFN block ---
        layernorm_kernel<<<MTOK/8, 256>>>(x, h, ln2_w + l * DMODEL, ln2_b + l * DMODEL);
        gemm_f16<128,EPI_GELU><<<pgrid(t_f1), 256, 98304>>>(
            h, w1 + (size_t)l*DFF*DMODEL, nullptr, f, MTOK, DFF, DMODEL);
        gemm_f16<64,EPI_ADD><<<pgrid(t_f2), 256, 73728>>>(
            f, w2 + (size_t)l*DMODEL*DFF, x, nullptr, MTOK, DMODEL, DFF);
    }

    layernorm_kernel<<<MTOK/8, 256>>>(x, h, lnf_w, lnf_b);
    gemm_f16<128,EPI_STORE><<<pgrid(t_lm), 256, 98304>>>(
        h, eh, out, nullptr, MTOK, VOC, DMODEL);
}

// round 16
// speedup vs baseline: 1.0443x; 1.0443x over previous
#include <cuda_runtime.h>
#include <cuda_fp16.h>
#include <math.h>
#include <stdint.h>

// ---------------- problem constants ----------------
#define NL     6
#define DMODEL 1024
#define DFF    4096
#define VOC    32000
#define NH     16
#define HDIM   64
#define BATCH  2
#define TSEQ   1024
#define MTOK   (BATCH*TSEQ)   // 2048

// ---------------- scratch (static device globals; no allocation) ----------------
__device__ float g_x[MTOK * DMODEL];

__device__ __align__(16) half g_h  [MTOK * DMODEL];
__device__ __align__(16) half g_qkv[(size_t)MTOK * 3 * DMODEL];
__device__ __align__(16) half g_o  [MTOK * DMODEL];
__device__ __align__(16) half g_f  [(size_t)MTOK * DFF];

__device__ __align__(16) half g_wq[(size_t)NL*3*DMODEL*DMODEL];
__device__ __align__(16) half g_wo[(size_t)NL*DMODEL*DMODEL];
__device__ __align__(16) half g_w1[(size_t)NL*DFF*DMODEL];
__device__ __align__(16) half g_w2[(size_t)NL*DMODEL*DFF];
__device__ __align__(16) half g_eh[(size_t)VOC*DMODEL];

// ---------------- helpers ----------------
__device__ __forceinline__ uint32_t packh(half a, half b) {
    __half2 t; t.x = a; t.y = b;
    return *(uint32_t*)&t;
}

__device__ __forceinline__ void cp_async16(uint32_t s, const void* g) {
    asm volatile("cp.async.cg.shared.global [%0], [%1], 16;\n" :: "r"(s), "l"(g));
}
__device__ __forceinline__ void cp_commit() { asm volatile("cp.async.commit_group;\n"); }
template<int N> __device__ __forceinline__ void cp_wait() {
    asm volatile("cp.async.wait_group %0;\n" :: "n"(N));
}

__device__ __forceinline__ void ldsm4(uint32_t* r, uint32_t addr) {
    asm volatile("ldmatrix.sync.aligned.m8n8.x4.shared.b16 {%0,%1,%2,%3}, [%4];\n"
        : "=r"(r[0]), "=r"(r[1]), "=r"(r[2]), "=r"(r[3]) : "r"(addr));
}
__device__ __forceinline__ void ldsm4t(uint32_t* r, uint32_t addr) {
    asm volatile("ldmatrix.sync.aligned.m8n8.x4.trans.shared.b16 {%0,%1,%2,%3}, [%4];\n"
        : "=r"(r[0]), "=r"(r[1]), "=r"(r[2]), "=r"(r[3]) : "r"(addr));
}

__device__ __forceinline__ void mma16816(float* c, const uint32_t* a, uint32_t b0, uint32_t b1) {
    asm volatile(
        "mma.sync.aligned.m16n8k16.row.col.f32.f16.f16.f32 "
        "{%0,%1,%2,%3}, {%4,%5,%6,%7}, {%8,%9}, {%0,%1,%2,%3};\n"
        : "+f"(c[0]), "+f"(c[1]), "+f"(c[2]), "+f"(c[3])
        : "r"(a[0]), "r"(a[1]), "r"(a[2]), "r"(a[3]), "r"(b0), "r"(b1));
}

// ---------------- fused fp32 -> fp16 conversion (8 elems/thread, MLP=2) ----------------
__global__ __launch_bounds__(256) void cvt_all(
    const float* __restrict__ x0, half* __restrict__ h0, size_t n0,
    const float* __restrict__ x1, half* __restrict__ h1, size_t n1,
    const float* __restrict__ x2, half* __restrict__ h2, size_t n2,
    const float* __restrict__ x3, half* __restrict__ h3, size_t n3,
    const float* __restrict__ x4, half* __restrict__ h4, size_t n4)
{
    size_t i = ((size_t)blockIdx.x * 256 + threadIdx.x) * 8;
    const float* s; half* d;
    if (i < n0)              { s = x0; d = h0; }
    else if ((i -= n0) < n1) { s = x1; d = h1; }
    else if ((i -= n1) < n2) { s = x2; d = h2; }
    else if ((i -= n2) < n3) { s = x3; d = h3; }
    else { i -= n3; if (i >= n4) return; s = x4; d = h4; }
    float4 va = *(const float4*)(s + i);
    float4 vb = *(const float4*)(s + i + 4);
    uint4 o;
    o.x = packh(__float2half(va.x), __float2half(va.y));
    o.y = packh(__float2half(va.z), __float2half(va.w));
    o.z = packh(__float2half(vb.x), __float2half(vb.y));
    o.w = packh(__float2half(vb.z), __float2half(vb.w));
    *(uint4*)(d + i) = o;
}

// ---------------- fp16 GEMM (mma.sync), BK=64, 3-stage, fragment double-buffer ----------------
// C[M,N] = A[M,K] * B[N,K]^T
// BM x 128 block, BK=64, 256 threads (8 warps, 2x4), warp tile (BM/2) x 32.
#define EPI_STORE  0
#define EPI_ADD    1
#define EPI_GELU   2
#define EPI_STOREH 3

template<int BM, int EPI>
__global__ __launch_bounds__(256, 2) void gemm_f16(
    const half* __restrict__ A, const half* __restrict__ B,
    float* __restrict__ C, half* __restrict__ Ch,
    int M, int N, int K)
{
    constexpr int NS = 3;                        // pipeline stages
    constexpr int MT = BM / 32;                  // m-tiles (16-row) per warp
    constexpr uint32_t ABYTES = (uint32_t)BM * 128;
    constexpr uint32_t STAGE  = ABYTES + 16384u; // [A | B 16KB] (rows x 128B)

    extern __shared__ uint8_t smem[];
    const uint32_t smem_u32 = (uint32_t)__cvta_generic_to_shared(smem);

    const int tid  = threadIdx.x;
    const int lane = tid & 31;
    const int wid  = tid >> 5;
    const int wm   = wid & 1;
    const int wn   = wid >> 1;
    const int bm   = blockIdx.y * BM;
    const int bn   = blockIdx.x * 128;

    const half* Ab = A + (size_t)bm * K;
    const half* Bb = B + (size_t)bn * K;

    float acc[MT][4][4];
#pragma unroll
    for (int a = 0; a < MT; a++)
#pragma unroll
        for (int b = 0; b < 4; b++)
#pragma unroll
            for (int c = 0; c < 4; c++) acc[a][b][c] = 0.f;

    const int ntiles = K >> 6;

    auto load_stage = [&](int st, int k0) {
        uint32_t base = smem_u32 + (uint32_t)st * STAGE;
#pragma unroll
        for (int i = 0; i < BM/32; i++) {            // A: BM*8 chunks
            int idx = tid * (BM/32) + i;
            int r = idx >> 3, c = idx & 7;
            size_t go = (size_t)r * K + k0 + c * 8;
            uint32_t so = base + r * 128 + (((uint32_t)(c ^ (r & 7))) << 4);
            cp_async16(so, Ab + go);
        }
#pragma unroll
        for (int i = 0; i < 4; i++) {                // B: 1024 chunks
            int idx = tid * 4 + i;
            int r = idx >> 3, c = idx & 7;
            size_t go = (size_t)r * K + k0 + c * 8;
            uint32_t so = base + ABYTES + r * 128 + (((uint32_t)(c ^ (r & 7))) << 4);
            cp_async16(so, Bb + go);
        }
    };

    // prologue: fill NS-1 stages, one commit group each
#pragma unroll
    for (int t = 0; t < NS - 1; t++) {
        load_stage(t, t << 6);
        cp_commit();
    }

    uint32_t af[2][MT][4], bf[2][2][4];

    int st = 0, stn = NS - 1;
    for (int t = 0; t < ntiles; t++) {
        cp_wait<NS - 2>();                 // stage t's group complete
        __syncthreads();                   // all warps done reading prev stage

        int tn = t + NS - 1;
        if (tn < ntiles) load_stage(stn, tn << 6);
        cp_commit();                       // always commit (empty groups in tail)

        const uint32_t bA = smem_u32 + (uint32_t)st * STAGE;
        const uint32_t bB = bA + ABYTES;

        auto load_frags = [&](int buf, int s) {
#pragma unroll
            for (int mt = 0; mt < MT; mt++) {
                int row = wm * (BM/2) + mt * 16 + (lane & 15);
                int ch  = 2 * s + (lane >> 4);
                uint32_t off = row * 128 + (((uint32_t)(ch ^ (row & 7))) << 4);
                ldsm4(af[buf][mt], bA + off);
            }
#pragma unroll
            for (int p = 0; p < 2; p++) {
                int row = wn * 32 + p * 16 + (lane & 15);
                int ch  = 2 * s + (lane >> 4);
                uint32_t off = row * 128 + (((uint32_t)(ch ^ (row & 7))) << 4);
                ldsm4(bf[buf][p], bB + off);
            }
        };

        load_frags(0, 0);
#pragma unroll
        for (int s = 0; s < 4; s++) {
            if (s < 3) load_frags((s + 1) & 1, s + 1);   // prefetch next slice
            const int cb = s & 1;
#pragma unroll
            for (int mt = 0; mt < MT; mt++)
#pragma unroll
                for (int nt = 0; nt < 4; nt++) {
                    int p = nt >> 1, q = nt & 1;
                    mma16816(acc[mt][nt], af[cb][mt], bf[cb][p][q], bf[cb][p][q + 2]);
                }
        }

        if (++st == NS) st = 0;
        if (++stn == NS) stn = 0;
    }

    __syncthreads();

    // --- epilogue ---
#pragma unroll
    for (int mt = 0; mt < MT; mt++) {
#pragma unroll
        for (int nt = 0; nt < 4; nt++) {
            int row = bm + wm * (BM/2) + mt * 16 + (lane >> 2);
            int col = bn + wn * 32 + nt * 8 + (lane & 3) * 2;
            size_t i0 = (size_t)row * N + col;
            size_t i1 = i0 + (size_t)8 * N;
            float* c = acc[mt][nt];
            if (EPI == EPI_STORE) {
                *(float2*)(C + i0) = make_float2(c[0], c[1]);
                *(float2*)(C + i1) = make_float2(c[2], c[3]);
            } else if (EPI == EPI_ADD) {
                float2 o0 = *(const float2*)(C + i0);
                float2 o1 = *(const float2*)(C + i1);
                o0.x += c[0]; o0.y += c[1];
                o1.x += c[2]; o1.y += c[3];
                *(float2*)(C + i0) = o0;
                *(float2*)(C + i1) = o1;
            } else if (EPI == EPI_GELU) {
#pragma unroll
                for (int e = 0; e < 4; e += 2) {
                    size_t ii = (e == 0) ? i0 : i1;
                    float v0 = c[e], v1 = c[e+1];
                    float q0 = 0.5f * v0 * (1.f + erff(v0 * 0.70710678118654752f));
                    float q1 = 0.5f * v1 * (1.f + erff(v1 * 0.70710678118654752f));
                    *(uint32_t*)(Ch + ii) = packh(__float2half(q0), __float2half(q1));
                }
            } else {  // EPI_STOREH
                *(uint32_t*)(Ch + i0) = packh(__float2half(c[0]), __float2half(c[1]));
                *(uint32_t*)(Ch + i1) = packh(__float2half(c[2]), __float2half(c[3]));
            }
        }
    }
}

// ---------------- flash attention (single fp16, mma.sync, 3-stage KV) ----------------
__global__ __launch_bounds__(256) void flash_kernel(
    const half* __restrict__ qkv, half* __restrict__ o)
{
    extern __shared__ uint8_t fsm[];
    const uint32_t sb  = (uint32_t)__cvta_generic_to_shared(fsm);
    const uint32_t sQ  = sb;                  // 128 x 64 halves = 16KB
    const uint32_t sKV = sb + 16384;          // + stage*16384 : [K 8KB | V 8KB], 3 stages

    const int tid = threadIdx.x, lane = tid & 31, w = tid >> 5;
    const int qi = (int)gridDim.x - 1 - (int)blockIdx.x;   // big tiles first
    const int bh = blockIdx.y;
    const int b = bh >> 4, h = bh & 15;
    const int qbase = qi * 128;
    const int nkb = (qbase + 128) >> 6;       // always >= 2

    const size_t tb = (size_t)b * TSEQ;
    const half* Q_ = qkv + tb * 3 * DMODEL + h * HDIM;
    const half* K_ = Q_ + DMODEL;
    const half* V_ = Q_ + 2 * DMODEL;

    auto load_kv = [&](int buf, int kb) {
        uint32_t base = sKV + (uint32_t)buf * 16384;
#pragma unroll
        for (int i = 0; i < 2; i++) {
            int idx = tid * 2 + i;          // 0..511
            int r = idx >> 3, c = idx & 7;
            size_t go = (size_t)(kb * 64 + r) * 3 * DMODEL + c * 8;
            uint32_t so = r * 128 + (((uint32_t)(c ^ (r & 7))) << 4);
            cp_async16(base + so,        K_ + go);
            cp_async16(base + 8192 + so, V_ + go);
        }
    };

    // prologue: Q + KV0 in group 0, KV1 in group 1
#pragma unroll
    for (int i = 0; i < 4; i++) {
        int idx = tid * 4 + i;              // 0..1023
        int r = idx >> 3, c = idx & 7;
        size_t go = (size_t)(qbase + r) * 3 * DMODEL + c * 8;
        uint32_t so = r * 128 + (((uint32_t)(c ^ (r & 7))) << 4);
        cp_async16(sQ + so, Q_ + go);
    }
    load_kv(0, 0);
    cp_commit();                 // group 0
    load_kv(1, 1);
    cp_commit();                 // group 1

    cp_wait<1>();                // group 0 (Q + KV0) complete
    __syncthreads();

    uint32_t qf[4][4];
#pragma unroll
    for (int s = 0; s < 4; s++) {
        int r = 16 * w + (lane & 15);
        int c = 2 * s + (lane >> 4);
        uint32_t so = r * 128 + (((uint32_t)(c ^ (r & 7))) << 4);
        ldsm4(qf[s], sQ + so);
    }

    float oacc[8][4];
#pragma unroll
    for (int j = 0; j < 8; j++)
#pragma unroll
        for (int c = 0; c < 4; c++) oacc[j][c] = 0.f;
    float mrow0 = -1e30f, mrow1 = -1e30f, lrow0 = 0.f, lrow1 = 0.f;
    const int r0 = qbase + 16 * w + (lane >> 2);

    int st = 0, stn = 2;
    for (int kb = 0; kb < nkb; kb++) {
        cp_wait<1>();                       // group kb complete
        __syncthreads();                    // all warps done reading stage (kb-1)%3

        int tn = kb + 2;
        if (tn < nkb) load_kv(stn, tn);
        cp_commit();                        // always commit (empty in tail)

        if (kb * 64 <= qbase + 16 * w + 15) {
            uint32_t base = sKV + (uint32_t)st * 16384;
            float sacc[8][4];
#pragma unroll
            for (int j = 0; j < 8; j++)
#pragma unroll
                for (int c = 0; c < 4; c++) sacc[j][c] = 0.f;

#pragma unroll
            for (int p = 0; p < 4; p++) {
                int rr = 16 * p + (lane & 15);
#pragma unroll
                for (int s = 0; s < 4; s++) {
                    int cc = 2 * s + (lane >> 4);
                    uint32_t so = rr * 128 + (((uint32_t)(cc ^ (rr & 7))) << 4);
                    uint32_t k4[4];
                    ldsm4(k4, base + so);
                    mma16816(sacc[2*p],   qf[s], k4[0], k4[2]);
                    mma16816(sacc[2*p+1], qf[s], k4[1], k4[3]);
                }
            }
            int cbase = kb * 64 + 2 * (lane & 3);
#pragma unroll
            for (int j = 0; j < 8; j++) {
                int c0 = cbase + 8 * j;
                sacc[j][0] = (c0     <= r0    ) ? sacc[j][0] * 0.125f : -1e30f;
                sacc[j][1] = (c0 + 1 <= r0    ) ? sacc[j][1] * 0.125f : -1e30f;
                sacc[j][2] = (c0     <= r0 + 8) ? sacc[j][2] * 0.125f : -1e30f;
                sacc[j][3] = (c0 + 1 <= r0 + 8) ? sacc[j][3] * 0.125f : -1e30f;
            }
            float mx0 = -1e30f, mx1 = -1e30f;
#pragma unroll
            for (int j = 0; j < 8; j++) {
                mx0 = fmaxf(mx0, fmaxf(sacc[j][0], sacc[j][1]));
                mx1 = fmaxf(mx1, fmaxf(sacc[j][2], sacc[j][3]));
            }
            mx0 = fmaxf(mx0, __shfl_xor_sync(0xffffffffu, mx0, 1));
            mx0 = fmaxf(mx0, __shfl_xor_sync(0xffffffffu, mx0, 2));
            mx1 = fmaxf(mx1, __shfl_xor_sync(0xffffffffu, mx1, 1));
            mx1 = fmaxf(mx1, __shfl_xor_sync(0xffffffffu, mx1, 2));
            float mn0 = fmaxf(mrow0, mx0), mn1 = fmaxf(mrow1, mx1);
            float al0 = __expf(mrow0 - mn0), al1 = __expf(mrow1 - mn1);
            mrow0 = mn0; mrow1 = mn1;

            uint32_t ph[8][2];
            float ls0 = 0.f, ls1 = 0.f;
#pragma unroll
            for (int j = 0; j < 8; j++) {
                float p0 = __expf(sacc[j][0] - mn0);
                float p1 = __expf(sacc[j][1] - mn0);
                float p2 = __expf(sacc[j][2] - mn1);
                float p3 = __expf(sacc[j][3] - mn1);
                ls0 += p0 + p1; ls1 += p2 + p3;
                ph[j][0] = packh(__float2half(p0), __float2half(p1));
                ph[j][1] = packh(__float2half(p2), __float2half(p3));
            }
            ls0 += __shfl_xor_sync(0xffffffffu, ls0, 1);
            ls0 += __shfl_xor_sync(0xffffffffu, ls0, 2);
            ls1 += __shfl_xor_sync(0xffffffffu, ls1, 1);
            ls1 += __shfl_xor_sync(0xffffffffu, ls1, 2);
            lrow0 = lrow0 * al0 + ls0;
            lrow1 = lrow1 * al1 + ls1;
#pragma unroll
            for (int j = 0; j < 8; j++) {
                oacc[j][0] *= al0; oacc[j][1] *= al0;
                oacc[j][2] *= al1; oacc[j][3] *= al1;
            }
            // P @ V
#pragma unroll
            for (int pv = 0; pv < 4; pv++) {
#pragma unroll
                for (int s = 0; s < 4; s++) {
                    int tok = 16 * s + ((lane >> 3) & 1) * 8 + (lane & 7);
                    int dc  = 16 * pv + (lane >> 4) * 8;
                    uint32_t so = tok * 128 + ((((uint32_t)(dc >> 3)) ^ (uint32_t)(tok & 7)) << 4);
                    uint32_t v4[4];
                    ldsm4t(v4, base + 8192 + so);
                    uint32_t pa[4] = {ph[2*s][0], ph[2*s][1], ph[2*s+1][0], ph[2*s+1][1]};
                    mma16816(oacc[2*pv],   pa, v4[0], v4[1]);
                    mma16816(oacc[2*pv+1], pa, v4[2], v4[3]);
                }
            }
        }

        if (++st == 3) st = 0;
        if (++stn == 3) stn = 0;
    }

    float rl0 = 1.f / lrow0, rl1 = 1.f / lrow1;
    size_t ob0 = (tb + r0) * (size_t)DMODEL + h * HDIM + 2 * (lane & 3);
    size_t ob1 = ob0 + 8 * (size_t)DMODEL;
#pragma unroll
    for (int j = 0; j < 8; j++) {
        *(uint32_t*)(o + ob0 + 8 * j) =
            packh(__float2half(oacc[j][0] * rl0), __float2half(oacc[j][1] * rl0));
        *(uint32_t*)(o + ob1 + 8 * j) =
            packh(__float2half(oacc[j][2] * rl1), __float2half(oacc[j][3] * rl1));
    }
}

// ---------------- embedding ----------------
__global__ void embed_kernel(const int* __restrict__ idx,
                             const float* __restrict__ tok,
                             const float* __restrict__ pos,
                             float* __restrict__ x)
{
    int t = blockIdx.x;
    int token = idx[t];
    const float* tr = tok + (size_t)token * DMODEL;
    const float* pr = pos + (size_t)(t & (TSEQ - 1)) * DMODEL;
    float* xr = x + (size_t)t * DMODEL;
    for (int d = threadIdx.x; d < DMODEL; d += blockDim.x)
        xr[d] = tr[d] + pr[d];
}

// ---------------- layernorm: warp per row, 8 rows/CTA ----------------
__global__ __launch_bounds__(256) void layernorm_kernel(
    const float* __restrict__ x, half* __restrict__ y,
    const float* __restrict__ w, const float* __restrict__ bvec)
{
    int lane = threadIdx.x & 31, wid = threadIdx.x >> 5;
    int row = blockIdx.x * 8 + wid;
    const float4* px = (const float4*)(x + (size_t)row * DMODEL);

    float4 v[8];
    float s = 0.f, ss = 0.f;
#pragma unroll
    for (int c = 0; c < 8; c++) {
        v[c] = px[lane + c * 32];
        s  += v[c].x + v[c].y + v[c].z + v[c].w;
        ss += v[c].x*v[c].x + v[c].y*v[c].y + v[c].z*v[c].z + v[c].w*v[c].w;
    }
#pragma unroll
    for (int o = 16; o; o >>= 1) {
        s  += __shfl_xor_sync(0xffffffffu, s,  o);
        ss += __shfl_xor_sync(0xffffffffu, ss, o);
    }
    float mean = s * (1.f / DMODEL);
    float var  = ss * (1.f / DMODEL) - mean * mean;
    float inv  = rsqrtf(var + 1e-5f);

    half* py = y + (size_t)row * DMODEL;
#pragma unroll
    for (int c = 0; c < 8; c++) {
        int j = (lane + c * 32) * 4;
        float4 wv = *(const float4*)(w + j);
        float4 bv = *(const float4*)(bvec + j);
        float y0 = (v[c].x - mean) * inv * wv.x + bv.x;
        float y1 = (v[c].y - mean) * inv * wv.y + bv.y;
        float y2 = (v[c].z - mean) * inv * wv.z + bv.z;
        float y3 = (v[c].w - mean) * inv * wv.w + bv.w;
        uint2 pk;
        pk.x = packh(__float2half(y0), __float2half(y1));
        pk.y = packh(__float2half(y2), __float2half(y3));
        *(uint2*)(py + j) = pk;
    }
}

// ---------------- launch ----------------
extern "C" void kernel_launch(void* const* d_in, const int* in_sizes, int n_in,
                              void* d_out, int out_size)
{
    (void)in_sizes; (void)n_in; (void)out_size;
    const int*   idx     = (const int*)  d_in[0];
    const float* tok_emb = (const float*)d_in[1];
    const float* pos_emb = (const float*)d_in[2];
    const float* ln1_w   = (const float*)d_in[3];
    const float* ln1_b   = (const float*)d_in[4];
    const float* qkv_w   = (const float*)d_in[5];
    const float* out_w   = (const float*)d_in[6];
    const float* ln2_w   = (const float*)d_in[7];
    const float* ln2_b   = (const float*)d_in[8];
    const float* ffn1_w  = (const float*)d_in[9];
    const float* ffn2_w  = (const float*)d_in[10];
    const float* lnf_w   = (const float*)d_in[11];
    const float* lnf_b   = (const float*)d_in[12];
    float* out = (float*)d_out;

    float *x;
    half *h, *qv, *o, *f, *wq, *wo, *w1, *w2, *eh;
    cudaGetSymbolAddress((void**)&x,   g_x);
    cudaGetSymbolAddress((void**)&h,   g_h);
    cudaGetSymbolAddress((void**)&qv,  g_qkv);
    cudaGetSymbolAddress((void**)&o,   g_o);
    cudaGetSymbolAddress((void**)&f,   g_f);
    cudaGetSymbolAddress((void**)&wq,  g_wq);
    cudaGetSymbolAddress((void**)&wo,  g_wo);
    cudaGetSymbolAddress((void**)&w1,  g_w1);
    cudaGetSymbolAddress((void**)&w2,  g_w2);
    cudaGetSymbolAddress((void**)&eh,  g_eh);

    cudaFuncSetAttribute(gemm_f16<64, EPI_STOREH>, cudaFuncAttributeMaxDynamicSharedMemorySize, 73728);
    cudaFuncSetAttribute(gemm_f16<64, EPI_ADD>,    cudaFuncAttributeMaxDynamicSharedMemorySize, 73728);
    cudaFuncSetAttribute(gemm_f16<128,EPI_GELU>,   cudaFuncAttributeMaxDynamicSharedMemorySize, 98304);
    cudaFuncSetAttribute(gemm_f16<128,EPI_STORE>,  cudaFuncAttributeMaxDynamicSharedMemorySize, 98304);
    cudaFuncSetAttribute(flash_kernel,             cudaFuncAttributeMaxDynamicSharedMemorySize, 65536);

    // fused weight conversion (single fp16) — one kernel, 8 elems/thread
    {
        const size_t n0 = (size_t)NL*3*DMODEL*DMODEL;
        const size_t n1 = (size_t)NL*DMODEL*DMODEL;
        const size_t n2 = (size_t)NL*DFF*DMODEL;
        const size_t n3 = (size_t)NL*DMODEL*DFF;
        const size_t n4 = (size_t)VOC*DMODEL;
        const size_t total = n0 + n1 + n2 + n3 + n4;
        int blocks = (int)(total / 8 / 256);
        cvt_all<<<blocks, 256>>>(qkv_w, wq, n0, out_w, wo, n1,
                                 ffn1_w, w1, n2, ffn2_w, w2, n3,
                                 tok_emb, eh, n4);
    }

    embed_kernel<<<MTOK, 256>>>(idx, tok_emb, pos_emb, x);

    for (int l = 0; l < NL; l++) {
        // --- attention block ---
        layernorm_kernel<<<MTOK/8, 256>>>(x, h, ln1_w + l * DMODEL, ln1_b + l * DMODEL);
        gemm_f16<64,EPI_STOREH><<<dim3(3*DMODEL/128, MTOK/64), 256, 73728>>>(
            h, wq + (size_t)l*3*DMODEL*DMODEL, nullptr, qv, MTOK, 3*DMODEL, DMODEL);
        flash_kernel<<<dim3(TSEQ/128, BATCH*NH), 256, 65536>>>(qv, o);
        gemm_f16<64,EPI_ADD><<<dim3(DMODEL/128, MTOK/64), 256, 73728>>>(
            o, wo + (size_t)l*DMODEL*DMODEL, x, nullptr, MTOK, DMODEL, DMODEL);
        // --- FFN block ---
        layernorm_kernel<<<MTOK/8, 256>>>(x, h, ln2_w + l * DMODEL, ln2_b + l * DMODEL);
        gemm_f16<128,EPI_GELU><<<dim3(DFF/128, MTOK/128), 256, 98304>>>(
            h, w1 + (size_t)l*DFF*DMODEL, nullptr, f, MTOK, DFF, DMODEL);
        gemm_f16<64,EPI_ADD><<<dim3(DMODEL/128, MTOK/64), 256, 73728>>>(
            f, w2 + (size_t)l*DMODEL*DFF, x, nullptr, MTOK, DMODEL, DFF);
    }

    layernorm_kernel<<<MTOK/8, 256>>>(x, h, lnf_w, lnf_b);
    gemm_f16<128,EPI_STORE><<<dim3(VOC/128, MTOK/128), 256, 98304>>>(
        h, eh, out, nullptr, MTOK, VOC, DMODEL);
}

// round 17
// speedup vs baseline: 1.0617x; 1.0166x over previous
#include <cuda_runtime.h>
#include <cuda_fp16.h>
#include <math.h>
#include <stdint.h>

// ---------------- problem constants ----------------
#define NL     6
#define DMODEL 1024
#define DFF    4096
#define VOC    32000
#define NH     16
#define HDIM   64
#define BATCH  2
#define TSEQ   1024
#define MTOK   (BATCH*TSEQ)   // 2048

// ---------------- scratch (static device globals; no allocation) ----------------
__device__ float g_x[MTOK * DMODEL];

__device__ __align__(16) half g_h  [MTOK * DMODEL];
__device__ __align__(16) half g_qkv[(size_t)MTOK * 3 * DMODEL];
__device__ __align__(16) half g_o  [MTOK * DMODEL];
__device__ __align__(16) half g_f  [(size_t)MTOK * DFF];

__device__ __align__(16) half g_wq[(size_t)NL*3*DMODEL*DMODEL];
__device__ __align__(16) half g_wo[(size_t)NL*DMODEL*DMODEL];
__device__ __align__(16) half g_w1[(size_t)NL*DFF*DMODEL];
__device__ __align__(16) half g_w2[(size_t)NL*DMODEL*DFF];
__device__ __align__(16) half g_eh[(size_t)VOC*DMODEL];

// ---------------- helpers ----------------
__device__ __forceinline__ uint32_t packh(half a, half b) {
    __half2 t; t.x = a; t.y = b;
    return *(uint32_t*)&t;
}

__device__ __forceinline__ void cp_async16(uint32_t s, const void* g) {
    asm volatile("cp.async.cg.shared.global [%0], [%1], 16;\n" :: "r"(s), "l"(g));
}
__device__ __forceinline__ void cp_commit() { asm volatile("cp.async.commit_group;\n"); }
template<int N> __device__ __forceinline__ void cp_wait() {
    asm volatile("cp.async.wait_group %0;\n" :: "n"(N));
}

__device__ __forceinline__ void ldsm4(uint32_t* r, uint32_t addr) {
    asm volatile("ldmatrix.sync.aligned.m8n8.x4.shared.b16 {%0,%1,%2,%3}, [%4];\n"
        : "=r"(r[0]), "=r"(r[1]), "=r"(r[2]), "=r"(r[3]) : "r"(addr));
}
__device__ __forceinline__ void ldsm4t(uint32_t* r, uint32_t addr) {
    asm volatile("ldmatrix.sync.aligned.m8n8.x4.trans.shared.b16 {%0,%1,%2,%3}, [%4];\n"
        : "=r"(r[0]), "=r"(r[1]), "=r"(r[2]), "=r"(r[3]) : "r"(addr));
}

__device__ __forceinline__ void mma16816(float* c, const uint32_t* a, uint32_t b0, uint32_t b1) {
    asm volatile(
        "mma.sync.aligned.m16n8k16.row.col.f32.f16.f16.f32 "
        "{%0,%1,%2,%3}, {%4,%5,%6,%7}, {%8,%9}, {%0,%1,%2,%3};\n"
        : "+f"(c[0]), "+f"(c[1]), "+f"(c[2]), "+f"(c[3])
        : "r"(a[0]), "r"(a[1]), "r"(a[2]), "r"(a[3]), "r"(b0), "r"(b1));
}

// ---------------- fused fp32 -> fp16 conversion (8 elems/thread, MLP=2) ----------------
__global__ __launch_bounds__(256) void cvt_all(
    const float* __restrict__ x0, half* __restrict__ h0, size_t n0,
    const float* __restrict__ x1, half* __restrict__ h1, size_t n1,
    const float* __restrict__ x2, half* __restrict__ h2, size_t n2,
    const float* __restrict__ x3, half* __restrict__ h3, size_t n3,
    const float* __restrict__ x4, half* __restrict__ h4, size_t n4)
{
    size_t i = ((size_t)blockIdx.x * 256 + threadIdx.x) * 8;
    const float* s; half* d;
    if (i < n0)              { s = x0; d = h0; }
    else if ((i -= n0) < n1) { s = x1; d = h1; }
    else if ((i -= n1) < n2) { s = x2; d = h2; }
    else if ((i -= n2) < n3) { s = x3; d = h3; }
    else { i -= n3; if (i >= n4) return; s = x4; d = h4; }
    float4 va = *(const float4*)(s + i);
    float4 vb = *(const float4*)(s + i + 4);
    uint4 o;
    o.x = packh(__float2half(va.x), __float2half(va.y));
    o.y = packh(__float2half(va.z), __float2half(va.w));
    o.z = packh(__float2half(vb.x), __float2half(vb.y));
    o.w = packh(__float2half(vb.z), __float2half(vb.w));
    *(uint4*)(d + i) = o;
}

// ---------------- fp16 GEMM (mma.sync), BK=64, 3-stage cp.async ----------------
// C[M,N] = A[M,K] * B[N,K]^T
// BM x 128 block, BK=64, 256 threads (8 warps, 2x4), warp tile (BM/2) x 32.
#define EPI_STORE  0
#define EPI_ADD    1
#define EPI_GELU   2
#define EPI_STOREH 3

template<int BM, int EPI>
__global__ __launch_bounds__(256) void gemm_f16(
    const half* __restrict__ A, const half* __restrict__ B,
    float* __restrict__ C, half* __restrict__ Ch,
    int M, int N, int K)
{
    constexpr int NS = 3;                        // pipeline stages
    constexpr int MT = BM / 32;                  // m-tiles (16-row) per warp
    constexpr uint32_t ABYTES = (uint32_t)BM * 128;
    constexpr uint32_t STAGE  = ABYTES + 16384u; // [A | B 16KB] (rows x 128B)

    extern __shared__ uint8_t smem[];
    const uint32_t smem_u32 = (uint32_t)__cvta_generic_to_shared(smem);

    const int tid  = threadIdx.x;
    const int lane = tid & 31;
    const int wid  = tid >> 5;
    const int wm   = wid & 1;
    const int wn   = wid >> 1;
    const int bm   = blockIdx.y * BM;
    const int bn   = blockIdx.x * 128;

    const half* Ab = A + (size_t)bm * K;
    const half* Bb = B + (size_t)bn * K;

    float acc[MT][4][4];
#pragma unroll
    for (int a = 0; a < MT; a++)
#pragma unroll
        for (int b = 0; b < 4; b++)
#pragma unroll
            for (int c = 0; c < 4; c++) acc[a][b][c] = 0.f;

    const int ntiles = K >> 6;

    auto load_stage = [&](int st, int k0) {
        uint32_t base = smem_u32 + (uint32_t)st * STAGE;
#pragma unroll
        for (int i = 0; i < BM/32; i++) {            // A: BM*8 chunks
            int idx = tid * (BM/32) + i;
            int r = idx >> 3, c = idx & 7;
            size_t go = (size_t)r * K + k0 + c * 8;
            uint32_t so = base + r * 128 + (((uint32_t)(c ^ (r & 7))) << 4);
            cp_async16(so, Ab + go);
        }
#pragma unroll
        for (int i = 0; i < 4; i++) {                // B: 1024 chunks
            int idx = tid * 4 + i;
            int r = idx >> 3, c = idx & 7;
            size_t go = (size_t)r * K + k0 + c * 8;
            uint32_t so = base + ABYTES + r * 128 + (((uint32_t)(c ^ (r & 7))) << 4);
            cp_async16(so, Bb + go);
        }
    };

    // prologue: fill NS-1 stages, one commit group each
#pragma unroll
    for (int t = 0; t < NS - 1; t++) {
        load_stage(t, t << 6);
        cp_commit();
    }

    int st = 0, stn = NS - 1;
    for (int t = 0; t < ntiles; t++) {
        cp_wait<NS - 2>();                 // stage t's group complete
        __syncthreads();                   // all warps done reading prev stage

        int tn = t + NS - 1;
        if (tn < ntiles) load_stage(stn, tn << 6);
        cp_commit();                       // always commit (empty groups in tail)

        const uint32_t bA = smem_u32 + (uint32_t)st * STAGE;
        const uint32_t bB = bA + ABYTES;

#pragma unroll
        for (int s = 0; s < 4; s++) {
            uint32_t af[MT][4];
#pragma unroll
            for (int mt = 0; mt < MT; mt++) {
                int row = wm * (BM/2) + mt * 16 + (lane & 15);
                int ch  = 2 * s + (lane >> 4);
                uint32_t off = row * 128 + (((uint32_t)(ch ^ (row & 7))) << 4);
                ldsm4(af[mt], bA + off);
            }
            uint32_t bf[2][4];
#pragma unroll
            for (int p = 0; p < 2; p++) {
                int row = wn * 32 + p * 16 + (lane & 15);
                int ch  = 2 * s + (lane >> 4);
                uint32_t off = row * 128 + (((uint32_t)(ch ^ (row & 7))) << 4);
                ldsm4(bf[p], bB + off);
            }
#pragma unroll
            for (int mt = 0; mt < MT; mt++)
#pragma unroll
                for (int nt = 0; nt < 4; nt++) {
                    int p = nt >> 1, q = nt & 1;
                    mma16816(acc[mt][nt], af[mt], bf[p][q], bf[p][q + 2]);
                }
        }

        if (++st == NS) st = 0;
        if (++stn == NS) stn = 0;
    }

    __syncthreads();

    // --- epilogue ---
#pragma unroll
    for (int mt = 0; mt < MT; mt++) {
#pragma unroll
        for (int nt = 0; nt < 4; nt++) {
            int row = bm + wm * (BM/2) + mt * 16 + (lane >> 2);
            int col = bn + wn * 32 + nt * 8 + (lane & 3) * 2;
            size_t i0 = (size_t)row * N + col;
            size_t i1 = i0 + (size_t)8 * N;
            float* c = acc[mt][nt];
            if (EPI == EPI_STORE) {
                *(float2*)(C + i0) = make_float2(c[0], c[1]);
                *(float2*)(C + i1) = make_float2(c[2], c[3]);
            } else if (EPI == EPI_ADD) {
                float2 o0 = *(const float2*)(C + i0);
                float2 o1 = *(const float2*)(C + i1);
                o0.x += c[0]; o0.y += c[1];
                o1.x += c[2]; o1.y += c[3];
                *(float2*)(C + i0) = o0;
                *(float2*)(C + i1) = o1;
            } else if (EPI == EPI_GELU) {
#pragma unroll
                for (int e = 0; e < 4; e += 2) {
                    size_t ii = (e == 0) ? i0 : i1;
                    float v0 = c[e], v1 = c[e+1];
                    float q0 = 0.5f * v0 * (1.f + erff(v0 * 0.70710678118654752f));
                    float q1 = 0.5f * v1 * (1.f + erff(v1 * 0.70710678118654752f));
                    *(uint32_t*)(Ch + ii) = packh(__float2half(q0), __float2half(q1));
                }
            } else {  // EPI_STOREH
                *(uint32_t*)(Ch + i0) = packh(__float2half(c[0]), __float2half(c[1]));
                *(uint32_t*)(Ch + i1) = packh(__float2half(c[2]), __float2half(c[3]));
            }
        }
    }
}

// ---------------- flash attention (single fp16, mma.sync, 3-stage KV) ----------------
__global__ __launch_bounds__(256) void flash_kernel(
    const half* __restrict__ qkv, half* __restrict__ o)
{
    extern __shared__ uint8_t fsm[];
    const uint32_t sb  = (uint32_t)__cvta_generic_to_shared(fsm);
    const uint32_t sQ  = sb;                  // 128 x 64 halves = 16KB
    const uint32_t sKV = sb + 16384;          // + stage*16384 : [K 8KB | V 8KB], 3 stages

    const int tid = threadIdx.x, lane = tid & 31, w = tid >> 5;
    const int qi = (int)gridDim.x - 1 - (int)blockIdx.x;   // big tiles first
    const int bh = blockIdx.y;
    const int b = bh >> 4, h = bh & 15;
    const int qbase = qi * 128;
    const int nkb = (qbase + 128) >> 6;       // always >= 2

    const size_t tb = (size_t)b * TSEQ;
    const half* Q_ = qkv + tb * 3 * DMODEL + h * HDIM;
    const half* K_ = Q_ + DMODEL;
    const half* V_ = Q_ + 2 * DMODEL;

    auto load_kv = [&](int buf, int kb) {
        uint32_t base = sKV + (uint32_t)buf * 16384;
#pragma unroll
        for (int i = 0; i < 2; i++) {
            int idx = tid * 2 + i;          // 0..511
            int r = idx >> 3, c = idx & 7;
            size_t go = (size_t)(kb * 64 + r) * 3 * DMODEL + c * 8;
            uint32_t so = r * 128 + (((uint32_t)(c ^ (r & 7))) << 4);
            cp_async16(base + so,        K_ + go);
            cp_async16(base + 8192 + so, V_ + go);
        }
    };

    // prologue: Q + KV0 in group 0, KV1 in group 1
#pragma unroll
    for (int i = 0; i < 4; i++) {
        int idx = tid * 4 + i;              // 0..1023
        int r = idx >> 3, c = idx & 7;
        size_t go = (size_t)(qbase + r) * 3 * DMODEL + c * 8;
        uint32_t so = r * 128 + (((uint32_t)(c ^ (r & 7))) << 4);
        cp_async16(sQ + so, Q_ + go);
    }
    load_kv(0, 0);
    cp_commit();                 // group 0
    load_kv(1, 1);
    cp_commit();                 // group 1

    cp_wait<1>();                // group 0 (Q + KV0) complete
    __syncthreads();

    uint32_t qf[4][4];
#pragma unroll
    for (int s = 0; s < 4; s++) {
        int r = 16 * w + (lane & 15);
        int c = 2 * s + (lane >> 4);
        uint32_t so = r * 128 + (((uint32_t)(c ^ (r & 7))) << 4);
        ldsm4(qf[s], sQ + so);
    }

    float oacc[8][4];
#pragma unroll
    for (int j = 0; j < 8; j++)
#pragma unroll
        for (int c = 0; c < 4; c++) oacc[j][c] = 0.f;
    float mrow0 = -1e30f, mrow1 = -1e30f, lrow0 = 0.f, lrow1 = 0.f;
    const int r0 = qbase + 16 * w + (lane >> 2);

    int st = 0, stn = 2;
    for (int kb = 0; kb < nkb; kb++) {
        cp_wait<1>();                       // group kb complete
        __syncthreads();                    // all warps done reading stage (kb-1)%3

        int tn = kb + 2;
        if (tn < nkb) load_kv(stn, tn);
        cp_commit();                        // always commit (empty in tail)

        if (kb * 64 <= qbase + 16 * w + 15) {
            uint32_t base = sKV + (uint32_t)st * 16384;
            float sacc[8][4];
#pragma unroll
            for (int j = 0; j < 8; j++)
#pragma unroll
                for (int c = 0; c < 4; c++) sacc[j][c] = 0.f;

#pragma unroll
            for (int p = 0; p < 4; p++) {
                int rr = 16 * p + (lane & 15);
#pragma unroll
                for (int s = 0; s < 4; s++) {
                    int cc = 2 * s + (lane >> 4);
                    uint32_t so = rr * 128 + (((uint32_t)(cc ^ (rr & 7))) << 4);
                    uint32_t k4[4];
                    ldsm4(k4, base + so);
                    mma16816(sacc[2*p],   qf[s], k4[0], k4[2]);
                    mma16816(sacc[2*p+1], qf[s], k4[1], k4[3]);
                }
            }
            int cbase = kb * 64 + 2 * (lane & 3);
#pragma unroll
            for (int j = 0; j < 8; j++) {
                int c0 = cbase + 8 * j;
                sacc[j][0] = (c0     <= r0    ) ? sacc[j][0] * 0.125f : -1e30f;
                sacc[j][1] = (c0 + 1 <= r0    ) ? sacc[j][1] * 0.125f : -1e30f;
                sacc[j][2] = (c0     <= r0 + 8) ? sacc[j][2] * 0.125f : -1e30f;
                sacc[j][3] = (c0 + 1 <= r0 + 8) ? sacc[j][3] * 0.125f : -1e30f;
            }
            float mx0 = -1e30f, mx1 = -1e30f;
#pragma unroll
            for (int j = 0; j < 8; j++) {
                mx0 = fmaxf(mx0, fmaxf(sacc[j][0], sacc[j][1]));
                mx1 = fmaxf(mx1, fmaxf(sacc[j][2], sacc[j][3]));
            }
            mx0 = fmaxf(mx0, __shfl_xor_sync(0xffffffffu, mx0, 1));
            mx0 = fmaxf(mx0, __shfl_xor_sync(0xffffffffu, mx0, 2));
            mx1 = fmaxf(mx1, __shfl_xor_sync(0xffffffffu, mx1, 1));
            mx1 = fmaxf(mx1, __shfl_xor_sync(0xffffffffu, mx1, 2));
            float mn0 = fmaxf(mrow0, mx0), mn1 = fmaxf(mrow1, mx1);
            float al0 = __expf(mrow0 - mn0), al1 = __expf(mrow1 - mn1);
            mrow0 = mn0; mrow1 = mn1;

            uint32_t ph[8][2];
            float ls0 = 0.f, ls1 = 0.f;
#pragma unroll
            for (int j = 0; j < 8; j++) {
                float p0 = __expf(sacc[j][0] - mn0);
                float p1 = __expf(sacc[j][1] - mn0);
                float p2 = __expf(sacc[j][2] - mn1);
                float p3 = __expf(sacc[j][3] - mn1);
                ls0 += p0 + p1; ls1 += p2 + p3;
                ph[j][0] = packh(__float2half(p0), __float2half(p1));
                ph[j][1] = packh(__float2half(p2), __float2half(p3));
            }
            ls0 += __shfl_xor_sync(0xffffffffu, ls0, 1);
            ls0 += __shfl_xor_sync(0xffffffffu, ls0, 2);
            ls1 += __shfl_xor_sync(0xffffffffu, ls1, 1);
            ls1 += __shfl_xor_sync(0xffffffffu, ls1, 2);
            lrow0 = lrow0 * al0 + ls0;
            lrow1 = lrow1 * al1 + ls1;
#pragma unroll
            for (int j = 0; j < 8; j++) {
                oacc[j][0] *= al0; oacc[j][1] *= al0;
                oacc[j][2] *= al1; oacc[j][3] *= al1;
            }
            // P @ V
#pragma unroll
            for (int pv = 0; pv < 4; pv++) {
#pragma unroll
                for (int s = 0; s < 4; s++) {
                    int tok = 16 * s + ((lane >> 3) & 1) * 8 + (lane & 7);
                    int dc  = 16 * pv + (lane >> 4) * 8;
                    uint32_t so = tok * 128 + ((((uint32_t)(dc >> 3)) ^ (uint32_t)(tok & 7)) << 4);
                    uint32_t v4[4];
                    ldsm4t(v4, base + 8192 + so);
                    uint32_t pa[4] = {ph[2*s][0], ph[2*s][1], ph[2*s+1][0], ph[2*s+1][1]};
                    mma16816(oacc[2*pv],   pa, v4[0], v4[1]);
                    mma16816(oacc[2*pv+1], pa, v4[2], v4[3]);
                }
            }
        }

        if (++st == 3) st = 0;
        if (++stn == 3) stn = 0;
    }

    float rl0 = 1.f / lrow0, rl1 = 1.f / lrow1;
    size_t ob0 = (tb + r0) * (size_t)DMODEL + h * HDIM + 2 * (lane & 3);
    size_t ob1 = ob0 + 8 * (size_t)DMODEL;
#pragma unroll
    for (int j = 0; j < 8; j++) {
        *(uint32_t*)(o + ob0 + 8 * j) =
            packh(__float2half(oacc[j][0] * rl0), __float2half(oacc[j][1] * rl0));
        *(uint32_t*)(o + ob1 + 8 * j) =
            packh(__float2half(oacc[j][2] * rl1), __float2half(oacc[j][3] * rl1));
    }
}

// ---------------- fused embedding + layernorm (warp per row, 8 rows/CTA) ----------------
// x[row] = tok_emb[idx[row]] + pos_emb[row % T];  y[row] = LN(x[row]) in fp16.
// Identical reduction order to layernorm_kernel -> bit-identical h.
__global__ __launch_bounds__(256) void embed_ln_kernel(
    const int* __restrict__ idx,
    const float* __restrict__ tok, const float* __restrict__ pos,
    float* __restrict__ x, half* __restrict__ y,
    const float* __restrict__ w, const float* __restrict__ bvec)
{
    int lane = threadIdx.x & 31, wid = threadIdx.x >> 5;
    int row = blockIdx.x * 8 + wid;
    int token = idx[row];
    const float4* pt = (const float4*)(tok + (size_t)token * DMODEL);
    const float4* pp = (const float4*)(pos + (size_t)(row & (TSEQ - 1)) * DMODEL);
    float4* px = (float4*)(x + (size_t)row * DMODEL);

    float4 v[8];
    float s = 0.f, ss = 0.f;
#pragma unroll
    for (int c = 0; c < 8; c++) {
        float4 t4 = pt[lane + c * 32];
        float4 p4 = pp[lane + c * 32];
        v[c].x = t4.x + p4.x; v[c].y = t4.y + p4.y;
        v[c].z = t4.z + p4.z; v[c].w = t4.w + p4.w;
        px[lane + c * 32] = v[c];
        s  += v[c].x + v[c].y + v[c].z + v[c].w;
        ss += v[c].x*v[c].x + v[c].y*v[c].y + v[c].z*v[c].z + v[c].w*v[c].w;
    }
#pragma unroll
    for (int o = 16; o; o >>= 1) {
        s  += __shfl_xor_sync(0xffffffffu, s,  o);
        ss += __shfl_xor_sync(0xffffffffu, ss, o);
    }
    float mean = s * (1.f / DMODEL);
    float var  = ss * (1.f / DMODEL) - mean * mean;
    float inv  = rsqrtf(var + 1e-5f);

    half* py = y + (size_t)row * DMODEL;
#pragma unroll
    for (int c = 0; c < 8; c++) {
        int j = (lane + c * 32) * 4;
        float4 wv = *(const float4*)(w + j);
        float4 bv = *(const float4*)(bvec + j);
        float y0 = (v[c].x - mean) * inv * wv.x + bv.x;
        float y1 = (v[c].y - mean) * inv * wv.y + bv.y;
        float y2 = (v[c].z - mean) * inv * wv.z + bv.z;
        float y3 = (v[c].w - mean) * inv * wv.w + bv.w;
        uint2 pk;
        pk.x = packh(__float2half(y0), __float2half(y1));
        pk.y = packh(__float2half(y2), __float2half(y3));
        *(uint2*)(py + j) = pk;
    }
}

// ---------------- layernorm: warp per row, 8 rows/CTA ----------------
__global__ __launch_bounds__(256) void layernorm_kernel(
    const float* __restrict__ x, half* __restrict__ y,
    const float* __restrict__ w, const float* __restrict__ bvec)
{
    int lane = threadIdx.x & 31, wid = threadIdx.x >> 5;
    int row = blockIdx.x * 8 + wid;
    const float4* px = (const float4*)(x + (size_t)row * DMODEL);

    float4 v[8];
    float s = 0.f, ss = 0.f;
#pragma unroll
    for (int c = 0; c < 8; c++) {
        v[c] = px[lane + c * 32];
        s  += v[c].x + v[c].y + v[c].z + v[c].w;
        ss += v[c].x*v[c].x + v[c].y*v[c].y + v[c].z*v[c].z + v[c].w*v[c].w;
    }
#pragma unroll
    for (int o = 16; o; o >>= 1) {
        s  += __shfl_xor_sync(0xffffffffu, s,  o);
        ss += __shfl_xor_sync(0xffffffffu, ss, o);
    }
    float mean = s * (1.f / DMODEL);
    float var  = ss * (1.f / DMODEL) - mean * mean;
    float inv  = rsqrtf(var + 1e-5f);

    half* py = y + (size_t)row * DMODEL;
#pragma unroll
    for (int c = 0; c < 8; c++) {
        int j = (lane + c * 32) * 4;
        float4 wv = *(const float4*)(w + j);
        float4 bv = *(const float4*)(bvec + j);
        float y0 = (v[c].x - mean) * inv * wv.x + bv.x;
        float y1 = (v[c].y - mean) * inv * wv.y + bv.y;
        float y2 = (v[c].z - mean) * inv * wv.z + bv.z;
        float y3 = (v[c].w - mean) * inv * wv.w + bv.w;
        uint2 pk;
        pk.x = packh(__float2half(y0), __float2half(y1));
        pk.y = packh(__float2half(y2), __float2half(y3));
        *(uint2*)(py + j) = pk;
    }
}

// ---------------- launch ----------------
extern "C" void kernel_launch(void* const* d_in, const int* in_sizes, int n_in,
                              void* d_out, int out_size)
{
    (void)in_sizes; (void)n_in; (void)out_size;
    const int*   idx     = (const int*)  d_in[0];
    const float* tok_emb = (const float*)d_in[1];
    const float* pos_emb = (const float*)d_in[2];
    const float* ln1_w   = (const float*)d_in[3];
    const float* ln1_b   = (const float*)d_in[4];
    const float* qkv_w   = (const float*)d_in[5];
    const float* out_w   = (const float*)d_in[6];
    const float* ln2_w   = (const float*)d_in[7];
    const float* ln2_b   = (const float*)d_in[8];
    const float* ffn1_w  = (const float*)d_in[9];
    const float* ffn2_w  = (const float*)d_in[10];
    const float* lnf_w   = (const float*)d_in[11];
    const float* lnf_b   = (const float*)d_in[12];
    float* out = (float*)d_out;

    float *x;
    half *h, *qv, *o, *f, *wq, *wo, *w1, *w2, *eh;
    cudaGetSymbolAddress((void**)&x,   g_x);
    cudaGetSymbolAddress((void**)&h,   g_h);
    cudaGetSymbolAddress((void**)&qv,  g_qkv);
    cudaGetSymbolAddress((void**)&o,   g_o);
    cudaGetSymbolAddress((void**)&f,   g_f);
    cudaGetSymbolAddress((void**)&wq,  g_wq);
    cudaGetSymbolAddress((void**)&wo,  g_wo);
    cudaGetSymbolAddress((void**)&w1,  g_w1);
    cudaGetSymbolAddress((void**)&w2,  g_w2);
    cudaGetSymbolAddress((void**)&eh,  g_eh);

    cudaFuncSetAttribute(gemm_f16<64, EPI_STOREH>, cudaFuncAttributeMaxDynamicSharedMemorySize, 73728);
    cudaFuncSetAttribute(gemm_f16<64, EPI_ADD>,    cudaFuncAttributeMaxDynamicSharedMemorySize, 73728);
    cudaFuncSetAttribute(gemm_f16<128,EPI_GELU>,   cudaFuncAttributeMaxDynamicSharedMemorySize, 98304);
    cudaFuncSetAttribute(gemm_f16<128,EPI_STORE>,  cudaFuncAttributeMaxDynamicSharedMemorySize, 98304);
    cudaFuncSetAttribute(flash_kernel,             cudaFuncAttributeMaxDynamicSharedMemorySize, 65536);

    // fused weight conversion (single fp16) — one kernel, 8 elems/thread
    {
        const size_t n0 = (size_t)NL*3*DMODEL*DMODEL;
        const size_t n1 = (size_t)NL*DMODEL*DMODEL;
        const size_t n2 = (size_t)NL*DFF*DMODEL;
        const size_t n3 = (size_t)NL*DMODEL*DFF;
        const size_t n4 = (size_t)VOC*DMODEL;
        const size_t total = n0 + n1 + n2 + n3 + n4;
        int blocks = (int)(total / 8 / 256);
        cvt_all<<<blocks, 256>>>(qkv_w, wq, n0, out_w, wo, n1,
                                 ffn1_w, w1, n2, ffn2_w, w2, n3,
                                 tok_emb, eh, n4);
    }

    // fused embedding + layer-0 ln1
    embed_ln_kernel<<<MTOK/8, 256>>>(idx, tok_emb, pos_emb, x, h, ln1_w, ln1_b);

    for (int l = 0; l < NL; l++) {
        // --- attention block ---
        if (l > 0)
            layernorm_kernel<<<MTOK/8, 256>>>(x, h, ln1_w + l * DMODEL, ln1_b + l * DMODEL);
        gemm_f16<64,EPI_STOREH><<<dim3(3*DMODEL/128, MTOK/64), 256, 73728>>>(
            h, wq + (size_t)l*3*DMODEL*DMODEL, nullptr, qv, MTOK, 3*DMODEL, DMODEL);
        flash_kernel<<<dim3(TSEQ/128, BATCH*NH), 256, 65536>>>(qv, o);
        gemm_f16<64,EPI_ADD><<<dim3(DMODEL/128, MTOK/64), 256, 73728>>>(
            o, wo + (size_t)l*DMODEL*DMODEL, x, nullptr, MTOK, DMODEL, DMODEL);
        // --- FFN block ---
        layernorm_kernel<<<MTOK/8, 256>>>(x, h, ln2_w + l * DMODEL, ln2_b + l * DMODEL);
        gemm_f16<128,EPI_GELU><<<dim3(DFF/128, MTOK/128), 256, 98304>>>(
            h, w1 + (size_t)l*DFF*DMODEL, nullptr, f, MTOK, DFF, DMODEL);
        gemm_f16<64,EPI_ADD><<<dim3(DMODEL/128, MTOK/64), 256, 73728>>>(
            f, w2 + (size_t)l*DMODEL*DFF, x, nullptr, MTOK, DMODEL, DFF);
    }

    layernorm_kernel<<<MTOK/8, 256>>>(x, h, lnf_w, lnf_b);
    gemm_f16<128,EPI_STORE><<<dim3(VOC/128, MTOK/128), 256, 98304>>>(
        h, eh, out, nullptr, MTOK, VOC, DMODEL);
}